// round 13
// baseline (speedup 1.0000x reference)
#include <cuda_runtime.h>
#include <cstdint>

// Shapes (fixed by the problem instance)
#define B_  4
#define H_  96
#define W_  96
#define D_  96
#define NWH 12            // 96/8
#define NUM_WIN 1728     // 12*12*12
#define LEN_KEEP 691      // int(1728*0.4)
#define ELEMS_PER_OUT (B_*H_*W_*D_*32)   // 113,246,208 floats

#define NWTOT (B_ * NUM_WIN)             // 6912 windows total
#define NPAIR (NWTOT / 2)                // 3456 window pairs
#define TOTAL_BLOCKS (2 * NPAIR)         // 6912: xm pairs + mk pairs
#define NQUADS (NUM_WIN / 4)             // 432 float4s of noise per batch

// ---------------------------------------------------------------------------
// Single fused kernel, no inter-block synchronization.
// Block bid < NPAIR : writes the x_masked stream of windows {2p, 2p+1}
//                     (kept -> copy x, masked -> zeros).
// Block bid >= NPAIR: writes the mask stream of windows {2p, 2p+1}
//                     (kept -> 0.0, masked -> 1.0).
// kept decided in-block via the stable-argsort-equivalent rank:
//   rank_i = #{ j : noise_j < noise_i or (noise_j == noise_i and j < i) }
//   kept   = rank_i < LEN_KEEP
// Prologue: threads 0..431 each load ONE float4 of noise and compare its 4
// values against both window keys (counts packed 16+16); warp shfl-reduce,
// ONE barrier, 16-way smem sum.
// OCCUPANCY IS THE LEVER: __launch_bounds__(512, 3) caps regs at 42 so THREE
// blocks fit per SM (vs 2 at 46 regs) — resident neighbors' 128KB bodies
// hide each block's prologue latency at wave transitions. The copy path is
// chunked 4+4 float4 to keep live payload regs low.
// ---------------------------------------------------------------------------
__global__ void __launch_bounds__(512, 3)
fused_kernel(const float4* __restrict__ x,
             float4* __restrict__ out_xm,
             float4* __restrict__ out_mk,
             const float* __restrict__ noise) {
    __shared__ int wred[16];

    const int bid    = blockIdx.x;
    const bool is_xm = (bid < NPAIR);
    const int p  = is_xm ? bid : bid - NPAIR;  // pair index
    const int g0 = 2 * p;                      // first global window id
    const int b  = g0 / NUM_WIN;
    const int i0 = g0 - b * NUM_WIN;           // window index within batch
    const int i1 = i0 + 1;

    const int tid  = threadIdx.x;
    const int lane = tid & 31;
    const int wid  = tid >> 5;

    // ---- ranks of windows i0, i1 within batch b (packed 16+16) ----
    const float*  nb  = noise + b * NUM_WIN;
    const float4* nb4 = (const float4*)nb;     // b*1728 floats: 16B aligned
    const unsigned int v0 = __float_as_uint(__ldg(&nb[i0]));
    const unsigned int v1 = __float_as_uint(__ldg(&nb[i1]));

    int cnt = 0;
    if (tid < NQUADS) {
        const float4 q = __ldg(&nb4[tid]);     // one vector load per thread
        const int j0 = 4 * tid;
        const unsigned int u0 = __float_as_uint(q.x);
        const unsigned int u1 = __float_as_uint(q.y);
        const unsigned int u2 = __float_as_uint(q.z);
        const unsigned int u3 = __float_as_uint(q.w);
        // raw-bit compare is exact: noise in [0,1), all positive floats
        cnt += ((u0 < v0) || (u0 == v0 && (j0 + 0) < i0));
        cnt += ((u1 < v0) || (u1 == v0 && (j0 + 1) < i0));
        cnt += ((u2 < v0) || (u2 == v0 && (j0 + 2) < i0));
        cnt += ((u3 < v0) || (u3 == v0 && (j0 + 3) < i0));
        cnt += (((u0 < v1) || (u0 == v1 && (j0 + 0) < i1))) << 16;
        cnt += (((u1 < v1) || (u1 == v1 && (j0 + 1) < i1))) << 16;
        cnt += (((u2 < v1) || (u2 == v1 && (j0 + 2) < i1))) << 16;
        cnt += (((u3 < v1) || (u3 == v1 && (j0 + 3) < i1))) << 16;
    }
#pragma unroll
    for (int o = 16; o > 0; o >>= 1)
        cnt += __shfl_xor_sync(0xFFFFFFFFu, cnt, o);
    if (lane == 0) wred[wid] = cnt;
    __syncthreads();
    int packed = 0;
#pragma unroll
    for (int k = 0; k < 16; k++) packed += wred[k];
    const bool kept0 = (packed & 0xFFFF) < LEN_KEEP;
    const bool kept1 = ((unsigned)packed >> 16) < LEN_KEEP;

    // ---- per-thread segment geometry (same for both windows) ----
    const int seg   = tid >> 3;        // 0..63 window segment
    const int lane8 = tid & 7;
    const int dh = seg >> 3;
    const int dw = seg & 7;

#pragma unroll
    for (int wsel = 0; wsel < 2; wsel++) {
        const int i     = wsel ? i1 : i0;
        const bool kept = wsel ? kept1 : kept0;

        const int wd3 = i % NWH;
        const int r2  = i / NWH;
        const int ww3 = r2 % NWH;
        const int wh3 = r2 / NWH;
        const int h = wh3 * 8 + dh;
        const int w = ww3 * 8 + dw;
        // float4 base of this segment (8 voxels along d, 32 ch = 64 float4)
        const int s0 = (((b * H_ + h) * W_ + w) * D_ + wd3 * 8) * 8 + lane8;

        if (is_xm) {
            if (kept) {
                // chunked 4+4 to keep live registers under the 42-reg cap
#pragma unroll
                for (int c = 0; c < 2; c++) {
                    float4 v[4];
#pragma unroll
                    for (int k = 0; k < 4; k++)
                        v[k] = __ldcs(&x[s0 + (c * 4 + k) * 8]);
#pragma unroll
                    for (int k = 0; k < 4; k++)
                        __stcs(&out_xm[s0 + (c * 4 + k) * 8], v[k]);
                }
            } else {
                const float4 z = make_float4(0.f, 0.f, 0.f, 0.f);
#pragma unroll
                for (int k = 0; k < 8; k++)
                    __stcs(&out_xm[s0 + k * 8], z);
            }
        } else {
            const float fv = kept ? 0.0f : 1.0f;
            const float4 c = make_float4(fv, fv, fv, fv);
#pragma unroll
            for (int k = 0; k < 8; k++)
                __stcs(&out_mk[s0 + k * 8], c);
        }
    }
}

extern "C" void kernel_launch(void* const* d_in, const int* in_sizes, int n_in,
                              void* d_out, int out_size) {
    const float* x     = (const float*)d_in[0];   // [B,H,W,D,C] fp32
    const float* noise = (const float*)d_in[1];   // [B, 1728]   fp32
    float* out = (float*)d_out;                   // [x_masked | mask]

    fused_kernel<<<TOTAL_BLOCKS, 512>>>(
        (const float4*)x,
        (float4*)out,
        (float4*)(out + (long long)ELEMS_PER_OUT),
        noise);
}

// round 14
// speedup vs baseline: 1.0061x; 1.0061x over previous
#include <cuda_runtime.h>
#include <cstdint>

// Shapes (fixed by the problem instance)
#define B_  4
#define H_  96
#define W_  96
#define D_  96
#define NWH 12            // 96/8
#define NUM_WIN 1728      // 12*12*12
#define LEN_KEEP 691      // int(1728*0.4)
#define KSEL (LEN_KEEP-1) // 0-indexed rank of the threshold key
#define LEN_MASK (NUM_WIN - LEN_KEEP)    // 1037
#define ELEMS_PER_OUT (B_*H_*W_*D_*32)   // 113,246,208 floats

// phase blocks: ONE output stream of ONE HALF-window (32 KB) per block
#define COPY_BLOCKS (B_ * LEN_KEEP * 2)  // 5528: kept -> xm copy (1R:1W)
#define ONES_BLOCKS (B_ * LEN_MASK * 2)  // 8296: masked -> mk = 1 (pure W)
#define TOTAL_BLOCKS (2*COPY_BLOCKS + 2*ONES_BLOCKS)   // 27648

// window-ordered compact lists of global window ids (b*1728+i)
__device__ int g_kept_list[B_ * LEN_KEEP];
__device__ int g_masked_list[B_ * LEN_MASK];

// ---------------------------------------------------------------------------
// Kernel 1 (prep): O(n) selection + compaction, one block per batch.
// Fires the PDL trigger at entry so the phase grid launches concurrently.
// ---------------------------------------------------------------------------
__global__ void __launch_bounds__(1024)
prep_kernel(const float* __restrict__ noise) {
    if (threadIdx.x == 0) cudaTriggerProgrammaticLaunchCompletion();

    __shared__ unsigned int sbits[NUM_WIN];
    __shared__ int hist[2048];
    __shared__ int wsum[32];
    __shared__ int s_bucket, s_below;
    __shared__ unsigned long long cand[128];
    __shared__ int cand_cnt;
    __shared__ unsigned long long s_thresh;

    const int b   = blockIdx.x;
    const int tid = threadIdx.x;
    const int lane = tid & 31;
    const int wid  = tid >> 5;

    for (int t = tid; t < NUM_WIN; t += 1024)
        sbits[t] = __float_as_uint(noise[b * NUM_WIN + t]);
    hist[tid] = 0; hist[tid + 1024] = 0;
    if (tid == 0) cand_cnt = 0;
    __syncthreads();

    for (int t = tid; t < NUM_WIN; t += 1024) {
        float v = __uint_as_float(sbits[t]);
        int bk = (int)(v * 2048.0f);
        bk = bk < 0 ? 0 : (bk > 2047 ? 2047 : bk);
        atomicAdd(&hist[bk], 1);
    }
    __syncthreads();

    // ---- scan of 2048 bucket counts (2 buckets per thread) ----
    const int a0 = hist[2 * tid], a1 = hist[2 * tid + 1];
    const int ts = a0 + a1;
    int v = ts;
#pragma unroll
    for (int o = 1; o < 32; o <<= 1) {
        int u = __shfl_up_sync(0xFFFFFFFFu, v, o);
        if (lane >= o) v += u;
    }
    if (lane == 31) wsum[wid] = v;
    __syncthreads();
    if (wid == 0) {
        int w = wsum[lane];
#pragma unroll
        for (int o = 1; o < 32; o <<= 1) {
            int u = __shfl_up_sync(0xFFFFFFFFu, w, o);
            if (lane >= o) w += u;
        }
        wsum[lane] = w;
    }
    __syncthreads();
    const int incl = v + (wid > 0 ? wsum[wid - 1] : 0);
    const int excl_pair = incl - ts;
    if (KSEL >= excl_pair && KSEL < excl_pair + a0) { s_bucket = 2 * tid;     s_below = excl_pair; }
    const int e1 = excl_pair + a0;
    if (KSEL >= e1 && KSEL < e1 + a1)               { s_bucket = 2 * tid + 1; s_below = e1; }
    __syncthreads();

    // ---- gather candidates in the target bucket, rank them exactly ----
    const int tb = s_bucket;
    for (int t = tid; t < NUM_WIN; t += 1024) {
        float fv = __uint_as_float(sbits[t]);
        int bk = (int)(fv * 2048.0f);
        bk = bk < 0 ? 0 : (bk > 2047 ? 2047 : bk);
        if (bk == tb) {
            int p = atomicAdd(&cand_cnt, 1);
            if (p < 128)
                cand[p] = ((unsigned long long)sbits[t] << 11) | (unsigned)t;
        }
    }
    __syncthreads();
    const int m = cand_cnt < 128 ? cand_cnt : 128;
    const int need = KSEL - s_below;
    if (tid < m) {
        unsigned long long k = cand[tid];
        int c = 0;
        for (int j = 0; j < m; j++) c += (cand[j] < k);
        if (c == need) s_thresh = k;
    }
    __syncthreads();
    const unsigned long long thresh = s_thresh;

    // ---- window-ordered compaction: 864 threads x 2 consecutive windows ----
    int cnt = 0, kept0 = 0, kept1 = 0;
    if (tid < 864) {
        const int j0 = 2 * tid, j1 = 2 * tid + 1;
        unsigned long long k0 = ((unsigned long long)sbits[j0] << 11) | (unsigned)j0;
        unsigned long long k1 = ((unsigned long long)sbits[j1] << 11) | (unsigned)j1;
        kept0 = (k0 <= thresh);
        kept1 = (k1 <= thresh);
        cnt = kept0 + kept1;
    }
    int v2 = cnt;
#pragma unroll
    for (int o = 1; o < 32; o <<= 1) {
        int u = __shfl_up_sync(0xFFFFFFFFu, v2, o);
        if (lane >= o) v2 += u;
    }
    if (lane == 31 && wid < 27) wsum[wid] = v2;
    __syncthreads();
    if (wid == 0) {
        int w = (lane < 27) ? wsum[lane] : 0;
#pragma unroll
        for (int o = 1; o < 32; o <<= 1) {
            int u = __shfl_up_sync(0xFFFFFFFFu, w, o);
            if (lane >= o) w += u;
        }
        if (lane < 27) wsum[lane] = w;
    }
    __syncthreads();
    if (tid < 864) {
        const int incl2 = v2 + (wid > 0 ? wsum[wid - 1] : 0);
        const int excl  = incl2 - cnt;          // kept windows before 2*tid
        const int j0 = 2 * tid, j1 = 2 * tid + 1;
        const int gw = b * NUM_WIN;
        if (kept0) g_kept_list[b * LEN_KEEP + excl]          = gw + j0;
        else       g_masked_list[b * LEN_MASK + (j0 - excl)]   = gw + j0;
        const int kb1 = excl + kept0;
        if (kept1) g_kept_list[b * LEN_KEEP + kb1]           = gw + j1;
        else       g_masked_list[b * LEN_MASK + (j1 - kb1)]    = gw + j1;
    }
}

// ---------------------------------------------------------------------------
// Kernel 2: phase kernel, single-stream HALF-window blocks (256 threads,
// 32 KB per block — R6's launch shape, which showed the small inter-kernel
// gap, combined with R7's grouped single-stream ordering):
//   bid ranges: [copy kept->xm][ones masked->mk][zeros masked->xm]
//               [zeros kept->mk]
// 8 float4 per thread. Holds at cudaGridDependencySynchronize().
// ---------------------------------------------------------------------------
__global__ void __launch_bounds__(256)
phase_kernel(const float4* __restrict__ x,
             float4* __restrict__ out_xm,
             float4* __restrict__ out_mk) {
    const int bid = blockIdx.x;

    int phase, k;
    if (bid < COPY_BLOCKS)                          { phase = 0; k = bid; }
    else if (bid < COPY_BLOCKS + ONES_BLOCKS)       { phase = 1; k = bid - COPY_BLOCKS; }
    else if (bid < COPY_BLOCKS + 2 * ONES_BLOCKS)   { phase = 2; k = bid - COPY_BLOCKS - ONES_BLOCKS; }
    else                                            { phase = 3; k = bid - COPY_BLOCKS - 2 * ONES_BLOCKS; }
    const bool from_masked = (phase == 1) || (phase == 2);
    const int lk   = k >> 1;       // list index
    const int half = k & 1;        // which half-window (dh 0..3 / 4..7)

    const int t     = threadIdx.x;
    const int seg   = half * 32 + (t >> 3);   // 0..63 window segment
    const int lane8 = t & 7;
    const int dh = seg >> 3;
    const int dw = seg & 7;

    cudaGridDependencySynchronize();   // HW wait: prep's writes visible

    const int wglob = from_masked ? __ldg(&g_masked_list[lk])
                                  : __ldg(&g_kept_list[lk]);

    const int b   = wglob / NUM_WIN;
    const int i   = wglob - b * NUM_WIN;
    const int wd3 = i % NWH;
    const int r   = i / NWH;
    const int ww3 = r % NWH;
    const int wh3 = r / NWH;

    const int h = wh3 * 8 + dh;
    const int w = ww3 * 8 + dw;
    // float4 base of this segment (8 voxels along d, 32 channels = 64 float4)
    const int s0 = (((b * H_ + h) * W_ + w) * D_ + wd3 * 8) * 8 + lane8;

    if (phase == 0) {
        // kept: copy x -> xm
        float4 v[8];
#pragma unroll
        for (int kk = 0; kk < 8; kk++)
            v[kk] = __ldcs(&x[s0 + kk * 8]);
#pragma unroll
        for (int kk = 0; kk < 8; kk++)
            __stcs(&out_xm[s0 + kk * 8], v[kk]);
    } else {
        const float fv = (phase == 1) ? 1.0f : 0.0f;
        const float4 c = make_float4(fv, fv, fv, fv);
        float4* outp = (phase == 2) ? out_xm : out_mk;
#pragma unroll
        for (int kk = 0; kk < 8; kk++)
            __stcs(&outp[s0 + kk * 8], c);
    }
}

extern "C" void kernel_launch(void* const* d_in, const int* in_sizes, int n_in,
                              void* d_out, int out_size) {
    const float* x     = (const float*)d_in[0];   // [B,H,W,D,C] fp32
    const float* noise = (const float*)d_in[1];   // [B, 1728]   fp32
    float* out = (float*)d_out;                   // [x_masked | mask]

    prep_kernel<<<B_, 1024>>>(noise);

    // PDL launch: prep triggers completion at entry; phase grid ramps
    // concurrently and holds at cudaGridDependencySynchronize().
    cudaLaunchConfig_t cfg = {};
    cfg.gridDim  = dim3(TOTAL_BLOCKS);
    cfg.blockDim = dim3(256);
    cudaLaunchAttribute attrs[1];
    attrs[0].id = cudaLaunchAttributeProgrammaticStreamSerialization;
    attrs[0].val.programmaticStreamSerializationAllowed = 1;
    cfg.attrs = attrs;
    cfg.numAttrs = 1;
    cudaLaunchKernelEx(&cfg, phase_kernel,
                       (const float4*)x,
                       (float4*)out,
                       (float4*)(out + (long long)ELEMS_PER_OUT));
}